// round 6
// baseline (speedup 1.0000x reference)
#include <cuda_runtime.h>
#include <cuda_bf16.h>
#include <cstdint>

#define BB 2
#define LL 1024
#define DIN 768
#define DM 1536
#define DS 16
#define DD 96
#define NL 4
#define ROWS (BB*LL)   // 2048
#define VOCAB 32000
#define KW_IN (DIN/2)  // 384 words per row
#define KW_DM (DM/2)   // 768 words per row

// ---------------- scratch (static device globals; no allocation) ----------------
__device__ float g_seq[ROWS*DIN];
__device__ float g_ab [ROWS*2*DM];
__device__ float g_ac [ROWS*DM];
__device__ float g_Bm [ROWS*DS];
__device__ float g_Cm [ROWS*DS];
__device__ float g_dt [ROWS*DD];
__device__ float g_delta[ROWS*DM];
__device__ float g_wpack[NL*128*DM];

// packed bf16x2 hi/lo operands (pair-permuted order for MMA; 16B chunks contiguous)
__device__ unsigned g_xn_hi[ROWS*KW_IN],  g_xn_lo[ROWS*KW_IN];
__device__ unsigned g_so_hi[ROWS*KW_DM],  g_so_lo[ROWS*KW_DM];
__device__ unsigned g_wi_hi[NL*2*DM*KW_IN], g_wi_lo[NL*2*DM*KW_IN];
__device__ unsigned g_wo_hi[NL*DIN*KW_DM],  g_wo_lo[NL*DIN*KW_DM];
// tf32-rounded, pair-permuted operands for the head GEMM
__device__ float g_wh_tf[VOCAB*DIN];
__device__ float g_xn_tf[ROWS*DIN];

__device__ __forceinline__ float siluf(float x){ return x / (1.f + __expf(-x)); }
__device__ __forceinline__ float softplusf(float x){ return fmaxf(x,0.f) + log1pf(expf(-fabsf(x))); }

__device__ __forceinline__ unsigned pack_split(float x0, float x1, unsigned &lopair){
    __nv_bfloat16 h0 = __float2bfloat16(x0);
    __nv_bfloat16 h1 = __float2bfloat16(x1);
    float f0 = __bfloat162float(h0), f1 = __bfloat162float(h1);
    __nv_bfloat16 l0 = __float2bfloat16(x0 - f0);
    __nv_bfloat16 l1 = __float2bfloat16(x1 - f1);
    lopair = ((unsigned)__bfloat16_as_ushort(l1) << 16) | __bfloat16_as_ushort(l0);
    return ((unsigned)__bfloat16_as_ushort(h1) << 16) | __bfloat16_as_ushort(h0);
}

__device__ __forceinline__ float rna_tf32(float x){
    unsigned u; asm("cvt.rna.tf32.f32 %0, %1;" : "=r"(u) : "f"(x));
    return __uint_as_float(u);
}

__device__ __forceinline__ void mma_bf16(float* d, const unsigned* a, const unsigned* b){
    asm volatile(
      "mma.sync.aligned.m16n8k16.row.col.f32.bf16.bf16.f32 "
      "{%0,%1,%2,%3}, {%4,%5,%6,%7}, {%8,%9}, {%0,%1,%2,%3};\n"
      : "+f"(d[0]),"+f"(d[1]),"+f"(d[2]),"+f"(d[3])
      : "r"(a[0]),"r"(a[1]),"r"(a[2]),"r"(a[3]), "r"(b[0]),"r"(b[1]));
}
__device__ __forceinline__ void mma_tf32(float* d,
    unsigned a0, unsigned a1, unsigned a2, unsigned a3, unsigned b0, unsigned b1){
    asm volatile(
      "mma.sync.aligned.m16n8k8.row.col.f32.tf32.tf32.f32 "
      "{%0,%1,%2,%3}, {%4,%5,%6,%7}, {%8,%9}, {%0,%1,%2,%3};\n"
      : "+f"(d[0]),"+f"(d[1]),"+f"(d[2]),"+f"(d[3])
      : "r"(a0),"r"(a1),"r"(a2),"r"(a3), "r"(b0),"r"(b1));
}

__device__ __forceinline__ void cp16(void* s, const void* g){
    unsigned a = (unsigned)__cvta_generic_to_shared(s);
    asm volatile("cp.async.cg.shared.global [%0], [%1], 16;" :: "r"(a), "l"(g));
}

// ---------------- weight split: fp32 [Nrows,K] -> packed bf16x2 hi/lo ----------------
__global__ void split_kernel(const float* __restrict__ src, unsigned* __restrict__ hi,
                             unsigned* __restrict__ lo, int totalWords, int K){
    int idx = blockIdx.x*256 + threadIdx.x;
    if (idx >= totalWords) return;
    int Kw = K >> 1;
    int n = idx / Kw, w = idx - n*Kw;
    int k = 2*w;
    float x0 = src[(size_t)n*K + k], x1 = src[(size_t)n*K + k + 1];
    unsigned l; unsigned h = pack_split(x0, x1, l);
    hi[idx] = h; lo[idx] = l;
}

// ---------------- tf32 round + pair-permute: fp32 [Nrows,K] -> permuted tf32 ---------
// dst word at (g*16 + pos) comes from src col g*16 + c, pos(c) within 8-block:
// pos = ((c&3)<<1)|((c>>2)&1) so frag pairs (q, q+4) are adjacent.
__global__ void tf32_perm_kernel(const float* __restrict__ src, float* __restrict__ dst,
                                 int total, int K){
    int idx = blockIdx.x*256 + threadIdx.x;
    if (idx >= total) return;
    int n = idx / K, w = idx - n*K;
    int g = w >> 4, pos = w & 15;
    int kb = pos >> 3, p = pos & 7;
    int c = (kb << 3) | ((p & 1) << 2) | (p >> 1);
    dst[idx] = rna_tf32(src[(size_t)n*K + g*16 + c]);
}

// ---------------- embedding gather ----------------
__global__ void embed_kernel(const int* __restrict__ tok, const float* __restrict__ emb){
    int row = blockIdx.x;
    int t = tok[row];
    for (int c = threadIdx.x; c < DIN; c += blockDim.x)
        g_seq[row*DIN + c] = emb[t*DIN + c];
}

// ---------------- rmsnorm -> split bf16 hi/lo (+ optional permuted tf32) -------------
__global__ void rmsnorm_kernel(const float* __restrict__ in, const float* __restrict__ w,
                               unsigned* __restrict__ hi, unsigned* __restrict__ lo,
                               float* __restrict__ tf){
    int row = blockIdx.x;
    float ss = 0.f;
    #pragma unroll
    for (int i = 0; i < 3; i++){
        float x = in[row*DIN + threadIdx.x + i*256];
        ss += x*x;
    }
    #pragma unroll
    for (int off = 16; off > 0; off >>= 1) ss += __shfl_xor_sync(0xffffffffu, ss, off);
    __shared__ float red[8];
    if ((threadIdx.x & 31) == 0) red[threadIdx.x >> 5] = ss;
    __syncthreads();
    float ms = 0.f;
    #pragma unroll
    for (int i = 0; i < 8; i++) ms += red[i];
    float r = rsqrtf(ms * (1.f/768.f) + 1e-6f);
    for (int p = threadIdx.x; p < KW_IN; p += 256){
        int c = 2*p;
        float y0 = in[row*DIN + c]     * r * w[c];
        float y1 = in[row*DIN + c + 1] * r * w[c+1];
        unsigned l; unsigned h = pack_split(y0, y1, l);
        hi[row*KW_IN + p] = h; lo[row*KW_IN + p] = l;
        if (tf){
            #pragma unroll
            for (int e = 0; e < 2; e++){
                int cc = c + e;
                int g = cc >> 4, cw = cc & 15;
                int pos = ((cw >> 3) << 3) | (((cw & 7) & 3) << 1) | (((cw & 7) >> 2) & 1);
                tf[row*DIN + g*16 + pos] = rna_tf32(e ? y1 : y0);
            }
        }
    }
}

// ========== bf16x3 split GEMM, 4-stage cp.async ring, 1 barrier/iter ==========
// C[M,N] = A[M,K]@B[N,K]^T. 256 thr, 8 warps (4Mx2N), warp 32x64, BK=16.
// dyn smem: 4 stages x 4 arrays x 1024 words = 64KB. 2 CTAs/SM.
#define BF_STAGE_W (4*1024)
#define BF_SMEM (4*BF_STAGE_W*4)
__global__ void __launch_bounds__(256,2) gemm_bf16s_kernel(
    const unsigned* __restrict__ Ahi, const unsigned* __restrict__ Alo,
    const unsigned* __restrict__ Bhi, const unsigned* __restrict__ Blo,
    float* __restrict__ C, int M, int N, int K,
    const float* __restrict__ bias, const float* __restrict__ resid, int act)
{
    extern __shared__ unsigned smu[];
    int tid = threadIdx.x;
    int lane = tid & 31, warp = tid >> 5;
    int qr = lane >> 2, q = lane & 3;
    int m0 = (warp >> 1) * 32, n0 = (warp & 1) * 64;
    int brow = blockIdx.x * 128, bcol = blockIdx.y * 128;
    int Kw = K >> 1;
    int kt = K >> 4;

    const unsigned* bases[4] = {Ahi, Alo, Bhi, Blo};
    auto load_stage = [&](int j, int s){
        unsigned* stg = smu + s*BF_STAGE_W;
        #pragma unroll
        for (int i = 0; i < 4; i++){
            int cid = tid*4 + i;             // 0..1023
            int arr = cid >> 8;              // which operand array
            int c   = cid & 255;
            int row = c >> 1, half = c & 1;
            int gr  = (arr < 2 ? brow : bcol) + row;
            const unsigned* g = bases[arr] + (size_t)gr*Kw + j*8 + half*4;
            cp16(stg + arr*1024 + row*8 + half*4, g);
        }
        asm volatile("cp.async.commit_group;");
    };

    float acc[2][8][4];
    #pragma unroll
    for (int im = 0; im < 2; im++)
        #pragma unroll
        for (int jn = 0; jn < 8; jn++)
            #pragma unroll
            for (int e = 0; e < 4; e++) acc[im][jn][e] = 0.f;

    load_stage(0, 0);
    if (kt > 1) load_stage(1, 1);
    if (kt > 2) load_stage(2, 2);

    for (int j = 0; j < kt; j++){
        if (j + 2 < kt)      asm volatile("cp.async.wait_group 2;");
        else if (j + 1 < kt) asm volatile("cp.async.wait_group 1;");
        else                 asm volatile("cp.async.wait_group 0;");
        __syncthreads();
        if (j + 3 < kt) load_stage(j + 3, (j + 3) & 3);

        unsigned* stg = smu + (j & 3)*BF_STAGE_W;
        unsigned ah[2][4], al[2][4];
        #pragma unroll
        for (int im = 0; im < 2; im++){
            int r0 = (m0 + im*16 + qr    )*8 + 2*q;
            int r1 = (m0 + im*16 + qr + 8)*8 + 2*q;
            uint2 h0 = *(const uint2*)&stg[r0];
            uint2 h1 = *(const uint2*)&stg[r1];
            ah[im][0] = h0.x; ah[im][1] = h1.x; ah[im][2] = h0.y; ah[im][3] = h1.y;
            uint2 l0 = *(const uint2*)&stg[1024 + r0];
            uint2 l1 = *(const uint2*)&stg[1024 + r1];
            al[im][0] = l0.x; al[im][1] = l1.x; al[im][2] = l0.y; al[im][3] = l1.y;
        }
        #pragma unroll
        for (int jn = 0; jn < 8; jn++){
            int rb = (n0 + jn*8 + qr)*8 + 2*q;
            uint2 bh2 = *(const uint2*)&stg[2048 + rb];
            uint2 bl2 = *(const uint2*)&stg[3072 + rb];
            unsigned bh[2] = {bh2.x, bh2.y};
            unsigned bl[2] = {bl2.x, bl2.y};
            #pragma unroll
            for (int im = 0; im < 2; im++) mma_bf16(acc[im][jn], ah[im], bh);
            #pragma unroll
            for (int im = 0; im < 2; im++) mma_bf16(acc[im][jn], ah[im], bl);
            #pragma unroll
            for (int im = 0; im < 2; im++) mma_bf16(acc[im][jn], al[im], bh);
        }
    }

    #pragma unroll
    for (int im = 0; im < 2; im++){
        #pragma unroll
        for (int h = 0; h < 2; h++){
            int m = brow + m0 + im*16 + qr + h*8;
            #pragma unroll
            for (int jn = 0; jn < 8; jn++){
                int n = bcol + n0 + jn*8 + 2*q;
                float v0 = acc[im][jn][h*2 + 0];
                float v1 = acc[im][jn][h*2 + 1];
                if (bias){ v0 += bias[n]; v1 += bias[n+1]; }
                if (act){ v0 = softplusf(v0); v1 = softplusf(v1); }
                if (resid){ v0 += resid[(size_t)m*N + n]; v1 += resid[(size_t)m*N + n + 1]; }
                *(float2*)&C[(size_t)m*N + n] = make_float2(v0, v1);
            }
        }
    }
}

// ========== TF32 single-pass GEMM (head): C[M,N] = A[M,K]@B[N,K]^T ==========
// Inputs pre-rounded (cvt.rna.tf32) and pair-permuted. 4-stage ring, BK=16.
// smem rows padded to 20 words (max 2-way LDS.64 conflict). 80KB dyn smem, 2 CTA/SM.
#define TFS 20
#define TF_ARR_W (128*TFS)          // 2560 words per operand
#define TF_STAGE_W (2*TF_ARR_W)     // 5120
#define TF_SMEM (4*TF_STAGE_W*4)    // 81920 bytes
__global__ void __launch_bounds__(256,2) gemm_tf32_kernel(
    const float* __restrict__ A, const float* __restrict__ Bw,
    float* __restrict__ C, int M, int N, int K)
{
    extern __shared__ float smf[];
    int tid = threadIdx.x;
    int lane = tid & 31, warp = tid >> 5;
    int qr = lane >> 2, q = lane & 3;
    int m0 = (warp >> 1) * 32, n0 = (warp & 1) * 64;
    int brow = blockIdx.x * 128, bcol = blockIdx.y * 128;
    int kt = K >> 4;

    auto load_stage = [&](int j, int s){
        float* stg = smf + s*TF_STAGE_W;
        #pragma unroll
        for (int i = 0; i < 4; i++){
            int cid = tid*4 + i;             // 0..1023
            int isB = cid >> 9;
            int c   = cid & 511;
            int row = c >> 2, c4 = c & 3;
            const float* g = (isB ? Bw + (size_t)(bcol+row)*K : A + (size_t)(brow+row)*K)
                             + j*16 + c4*4;
            cp16(stg + isB*TF_ARR_W + row*TFS + c4*4, g);
        }
        asm volatile("cp.async.commit_group;");
    };

    float acc[2][8][4];
    #pragma unroll
    for (int im = 0; im < 2; im++)
        #pragma unroll
        for (int jn = 0; jn < 8; jn++)
            #pragma unroll
            for (int e = 0; e < 4; e++) acc[im][jn][e] = 0.f;

    load_stage(0, 0);
    if (kt > 1) load_stage(1, 1);
    if (kt > 2) load_stage(2, 2);

    for (int j = 0; j < kt; j++){
        if (j + 2 < kt)      asm volatile("cp.async.wait_group 2;");
        else if (j + 1 < kt) asm volatile("cp.async.wait_group 1;");
        else                 asm volatile("cp.async.wait_group 0;");
        __syncthreads();
        if (j + 3 < kt) load_stage(j + 3, (j + 3) & 3);

        float* sA = smf + (j & 3)*TF_STAGE_W;
        float* sB = sA + TF_ARR_W;
        #pragma unroll
        for (int kb = 0; kb < 2; kb++){
            unsigned a[2][4];
            #pragma unroll
            for (int im = 0; im < 2; im++){
                float2 lo = *(const float2*)&sA[(m0 + im*16 + qr    )*TFS + kb*8 + 2*q];
                float2 hi = *(const float2*)&sA[(m0 + im*16 + qr + 8)*TFS + kb*8 + 2*q];
                a[im][0] = __float_as_uint(lo.x); a[im][1] = __float_as_uint(hi.x);
                a[im][2] = __float_as_uint(lo.y); a[im][3] = __float_as_uint(hi.y);
            }
            #pragma unroll
            for (int jn = 0; jn < 8; jn++){
                float2 bb = *(const float2*)&sB[(n0 + jn*8 + qr)*TFS + kb*8 + 2*q];
                unsigned b0 = __float_as_uint(bb.x), b1 = __float_as_uint(bb.y);
                #pragma unroll
                for (int im = 0; im < 2; im++)
                    mma_tf32(acc[im][jn], a[im][0],a[im][1],a[im][2],a[im][3], b0, b1);
            }
        }
    }

    #pragma unroll
    for (int im = 0; im < 2; im++){
        #pragma unroll
        for (int h = 0; h < 2; h++){
            int m = brow + m0 + im*16 + qr + h*8;
            #pragma unroll
            for (int jn = 0; jn < 8; jn++){
                int n = bcol + n0 + jn*8 + 2*q;
                *(float2*)&C[(size_t)m*N + n] =
                    make_float2(acc[im][jn][h*2 + 0], acc[im][jn][h*2 + 1]);
            }
        }
    }
}

// ---------------- FFMA SGEMM (small-K delta projection; full fp32) ----------------
__global__ void __launch_bounds__(256) gemm_nt_kernel(
    const float* __restrict__ A, const float* __restrict__ Bw, float* __restrict__ C,
    int M, int N, int K,
    const float* __restrict__ bias, const float* __restrict__ resid, int act)
{
    __shared__ float As[8][128];
    __shared__ float Bs[8][128];
    int tid = threadIdx.x;
    int tx = tid & 15, ty = tid >> 4;
    int brow = blockIdx.y * 128, bcol = blockIdx.x * 128;

    const float* Aptr = A  + (size_t)(brow + (tid >> 1)) * K + ((tid & 1) << 2);
    const float* Bptr = Bw + (size_t)(bcol + (tid >> 1)) * K + ((tid & 1) << 2);

    float acc[8][8];
    #pragma unroll
    for (int i = 0; i < 8; i++)
        #pragma unroll
        for (int j = 0; j < 8; j++) acc[i][j] = 0.f;

    int kt = K >> 3;
    float4 aReg = *(const float4*)Aptr;
    float4 bReg = *(const float4*)Bptr;

    for (int k = 0; k < kt; k++){
        int r = tid >> 1, c = (tid & 1) << 2;
        As[c+0][r]=aReg.x; As[c+1][r]=aReg.y; As[c+2][r]=aReg.z; As[c+3][r]=aReg.w;
        Bs[c+0][r]=bReg.x; Bs[c+1][r]=bReg.y; Bs[c+2][r]=bReg.z; Bs[c+3][r]=bReg.w;
        __syncthreads();
        if (k + 1 < kt){
            aReg = *(const float4*)(Aptr + (k+1)*8);
            bReg = *(const float4*)(Bptr + (k+1)*8);
        }
        #pragma unroll
        for (int kk = 0; kk < 8; kk++){
            float af[8], bf[8];
            #pragma unroll
            for (int i = 0; i < 8; i++) af[i] = As[kk][(i<<4)+ty];
            #pragma unroll
            for (int j = 0; j < 8; j++) bf[j] = Bs[kk][(j<<4)+tx];
            #pragma unroll
            for (int i = 0; i < 8; i++)
                #pragma unroll
                for (int j = 0; j < 8; j++)
                    acc[i][j] += af[i]*bf[j];
        }
        __syncthreads();
    }

    #pragma unroll
    for (int i = 0; i < 8; i++){
        int m = brow + (i<<4) + ty;
        #pragma unroll
        for (int j = 0; j < 8; j++){
            int n = bcol + (j<<4) + tx;
            float v = acc[i][j];
            if (bias)  v += bias[n];
            if (act)   v = softplusf(v);
            if (resid) v += resid[(size_t)m*N + n];
            C[(size_t)m*N + n] = v;
        }
    }
}

// ---------------- causal depthwise conv (K=4) + SiLU ----------------
__global__ void conv_silu_kernel(const float* __restrict__ cw, const float* __restrict__ cb){
    int d = blockIdx.x * blockDim.x + threadIdx.x;
    int row = blockIdx.y;
    int t = row & (LL-1);
    float4 w = *(const float4*)(cw + d*4);
    float acc = cb[d];
    const float* p = g_ab + (size_t)row*(2*DM) + d;
    if (t >= 3) acc += p[-3*2*DM]*w.x;
    if (t >= 2) acc += p[-2*2*DM]*w.y;
    if (t >= 1) acc += p[-1*2*DM]*w.z;
    acc += p[0]*w.w;
    g_ac[(size_t)row*DM + d] = siluf(acc);
}

// ---------------- pack sB|sC|sD0 into one [NL][128][DM] weight ----------------
__global__ void pack_kernel(const float* __restrict__ sB, const float* __restrict__ sC,
                            const float* __restrict__ sD0){
    int idx = blockIdx.x*256 + threadIdx.x;
    if (idx >= NL*128*DM) return;
    int k = idx % DM;
    int n = (idx / DM) & 127;
    int l = idx / (128*DM);
    float v;
    if (n < 16)      v = sB [((size_t)l*DS + n     )*DM + k];
    else if (n < 32) v = sC [((size_t)l*DS + (n-16))*DM + k];
    else             v = sD0[((size_t)l*DD + (n-32))*DM + k];
    g_wpack[idx] = v;
}

// ---------------- fused small projections: [16 rows] x [128 outs], K=1536 ----------------
#define SP_KC 64
__global__ void __launch_bounds__(256) small_proj_kernel(const float* __restrict__ wp){
    __shared__ float Ws[128][SP_KC+1];
    __shared__ float Xs[16][SP_KC+4];
    int m0  = blockIdx.x * 16;
    int tid = threadIdx.x;
    int n2  = tid & 63;
    int mh  = tid >> 6;
    float acc[2][4] = {{0.f,0.f,0.f,0.f},{0.f,0.f,0.f,0.f}};

    for (int k0 = 0; k0 < DM; k0 += SP_KC){
        #pragma unroll
        for (int j = 0; j < 8; j++){
            int idx = tid + j*256;
            int r = idx >> 4, c4 = (idx & 15) << 2;
            float4 v = *(const float4*)(wp + (size_t)r*DM + k0 + c4);
            Ws[r][c4+0]=v.x; Ws[r][c4+1]=v.y; Ws[r][c4+2]=v.z; Ws[r][c4+3]=v.w;
        }
        {
            int r = tid >> 4, c4 = (tid & 15) << 2;
            float4 v = *(const float4*)(g_ac + (size_t)(m0+r)*DM + k0 + c4);
            Xs[r][c4+0]=v.x; Xs[r][c4+1]=v.y; Xs[r][c4+2]=v.z; Xs[r][c4+3]=v.w;
        }
        __syncthreads();
        #pragma unroll 8
        for (int kk = 0; kk < SP_KC; kk++){
            float w0 = Ws[2*n2][kk], w1 = Ws[2*n2+1][kk];
            #pragma unroll
            for (int i = 0; i < 4; i++){
                float x = Xs[mh*4+i][kk];
                acc[0][i] += w0*x;
                acc[1][i] += w1*x;
            }
        }
        __syncthreads();
    }
    #pragma unroll
    for (int q = 0; q < 2; q++){
        int n = 2*n2 + q;
        #pragma unroll
        for (int i = 0; i < 4; i++){
            int m = m0 + mh*4 + i;
            float v = acc[q][i];
            if (n < 16)      g_Bm[m*DS + n]      = v;
            else if (n < 32) g_Cm[m*DS + (n-16)] = v;
            else             g_dt[m*DD + (n-32)] = v;
        }
    }
}

// ---------------- selective scan (writes split bf16 sout) ----------------
__global__ void scan_kernel(const float* __restrict__ A_log, const float* __restrict__ Dp){
    int lane = threadIdx.x & 31, warp = threadIdx.x >> 5;
    int s = lane & 15;
    int d = blockIdx.x*8 + warp*2 + (lane >> 4);
    int b = blockIdx.y;
    float Acoef = -expf(A_log[d*DS + s]);
    float Dv = Dp[d];
    int base  = (b*LL)*DM + d;
    int baseS = (b*LL)*DS + s;
    int baseG = (b*LL)*(2*DM) + DM + d;
    float dlt = g_delta[base], av = g_ac[base];
    float Bv = g_Bm[baseS], Cv = g_Cm[baseS];
    float gv = g_ab[baseG];
    float h = 0.f;
    int p = blockIdx.x*4 + warp;            // d-pair index within DM/2
    int wbase = (b*LL)*KW_DM + p;
    for (int t = 0; t < LL; t++){
        float dc = dlt, a_c = av, bc = Bv, cc = Cv, gc = gv;
        if (t + 1 < LL){
            base += DM; baseS += DS; baseG += 2*DM;
            dlt = g_delta[base]; av = g_ac[base];
            Bv = g_Bm[baseS];   Cv = g_Cm[baseS];
            gv = g_ab[baseG];
        }
        h = __expf(dc*Acoef)*h + dc*bc*a_c;
        float c = h*cc;
        c += __shfl_xor_sync(0xffffffffu, c, 8);
        c += __shfl_xor_sync(0xffffffffu, c, 4);
        c += __shfl_xor_sync(0xffffffffu, c, 2);
        c += __shfl_xor_sync(0xffffffffu, c, 1);
        float o = (c + Dv*a_c) * siluf(gc);
        float o2 = __shfl_xor_sync(0xffffffffu, o, 16);
        if (lane == 0){
            unsigned l; unsigned hh = pack_split(o, o2, l);
            g_so_hi[wbase + t*KW_DM] = hh;
            g_so_lo[wbase + t*KW_DM] = l;
        }
    }
}

// ---------------- launch ----------------
extern "C" void kernel_launch(void* const* d_in, const int* in_sizes, int n_in,
                              void* d_out, int out_size)
{
    const int*   tok      = (const int*)  d_in[0];
    const float* emb      = (const float*)d_in[1];
    const float* in_proj  = (const float*)d_in[2];
    const float* out_proj = (const float*)d_in[3];
    const float* sB       = (const float*)d_in[4];
    const float* sC       = (const float*)d_in[5];
    const float* sD0      = (const float*)d_in[6];
    const float* sD1w     = (const float*)d_in[7];
    const float* sD1b     = (const float*)d_in[8];
    const float* cw       = (const float*)d_in[9];
    const float* cb       = (const float*)d_in[10];
    const float* A_log    = (const float*)d_in[11];
    const float* Dp       = (const float*)d_in[12];
    const float* norm_w   = (const float*)d_in[13];
    const float* norm_f   = (const float*)d_in[14];
    const float* head_w   = (const float*)d_in[15];
    float* out = (float*)d_out;

    float *seq,*ab,*ac,*dt,*delta,*wpack,*whtf,*xntf;
    unsigned *xnh,*xnl,*soh,*sol,*wih,*wil,*woh,*wol;
    cudaGetSymbolAddress((void**)&seq,   g_seq);
    cudaGetSymbolAddress((void**)&ab,    g_ab);
    cudaGetSymbolAddress((void**)&ac,    g_ac);
    cudaGetSymbolAddress((void**)&dt,    g_dt);
    cudaGetSymbolAddress((void**)&delta, g_delta);
    cudaGetSymbolAddress((void**)&wpack, g_wpack);
    cudaGetSymbolAddress((void**)&whtf,  g_wh_tf);
    cudaGetSymbolAddress((void**)&xntf,  g_xn_tf);
    cudaGetSymbolAddress((void**)&xnh, g_xn_hi); cudaGetSymbolAddress((void**)&xnl, g_xn_lo);
    cudaGetSymbolAddress((void**)&soh, g_so_hi); cudaGetSymbolAddress((void**)&sol, g_so_lo);
    cudaGetSymbolAddress((void**)&wih, g_wi_hi); cudaGetSymbolAddress((void**)&wil, g_wi_lo);
    cudaGetSymbolAddress((void**)&woh, g_wo_hi); cudaGetSymbolAddress((void**)&wol, g_wo_lo);

    cudaFuncSetAttribute(gemm_bf16s_kernel, cudaFuncAttributeMaxDynamicSharedMemorySize, BF_SMEM);
    cudaFuncSetAttribute(gemm_tf32_kernel,  cudaFuncAttributeMaxDynamicSharedMemorySize, TF_SMEM);

    embed_kernel<<<ROWS, 256>>>(tok, emb);
    pack_kernel<<<(NL*128*DM + 255)/256, 256>>>(sB, sC, sD0);
    split_kernel<<<(NL*2*DM*KW_IN + 255)/256, 256>>>(in_proj,  wih, wil, NL*2*DM*KW_IN, DIN);
    split_kernel<<<(NL*DIN*KW_DM  + 255)/256, 256>>>(out_proj, woh, wol, NL*DIN*KW_DM,  DM);
    tf32_perm_kernel<<<(VOCAB*DIN + 255)/256, 256>>>(head_w, whtf, VOCAB*DIN, DIN);

    for (int l = 0; l < NL; l++){
        rmsnorm_kernel<<<ROWS, 256>>>(seq, norm_w + l*DIN, xnh, xnl, nullptr);
        // ab = xn @ in_proj^T   (2048 x 3072, K=768)
        gemm_bf16s_kernel<<<dim3(ROWS/128, 2*DM/128), 256, BF_SMEM>>>(
            xnh, xnl, wih + (size_t)l*2*DM*KW_IN, wil + (size_t)l*2*DM*KW_IN,
            ab, ROWS, 2*DM, DIN, nullptr, nullptr, 0);
        conv_silu_kernel<<<dim3(DM/256, ROWS), 256>>>(cw + l*DM*4, cb + l*DM);
        small_proj_kernel<<<ROWS/16, 256>>>(wpack + (size_t)l*128*DM);
        // delta = softplus(dt @ sD1w^T + sD1b)   (2048 x 1536, K=96)  [fp32 FFMA]
        gemm_nt_kernel<<<dim3(DM/128, ROWS/128), 256>>>(
            dt, sD1w + (size_t)l*DM*DD, delta, ROWS, DM, DD, sD1b + l*DM, nullptr, 1);
        scan_kernel<<<dim3(DM/8, BB), 128>>>(A_log + (size_t)l*DM*DS, Dp + l*DM);
        // seq = sout @ out_proj^T + seq   (2048 x 768, K=1536)
        gemm_bf16s_kernel<<<dim3(ROWS/128, DIN/128), 256, BF_SMEM>>>(
            soh, sol, woh + (size_t)l*DIN*KW_DM, wol + (size_t)l*DIN*KW_DM,
            seq, ROWS, DIN, DM, nullptr, seq, 0);
    }

    rmsnorm_kernel<<<ROWS, 256>>>(seq, norm_f, xnh, xnl, xntf);
    // logits = xn @ head_w^T   (2048 x 32000, K=768)  [TF32 single pass]
    gemm_tf32_kernel<<<dim3(ROWS/128, VOCAB/128), 256, TF_SMEM>>>(
        xntf, whtf, out, ROWS, VOCAB, DIN);
}

// round 7
// speedup vs baseline: 1.3217x; 1.3217x over previous
#include <cuda_runtime.h>
#include <cuda_bf16.h>
#include <cuda_fp16.h>
#include <cstdint>

#define BB 2
#define LL 1024
#define DIN 768
#define DM 1536
#define DS 16
#define DD 96
#define NL 4
#define ROWS (BB*LL)   // 2048
#define VOCAB 32000
#define KW_IN (DIN/2)  // 384 words per row
#define KW_DM (DM/2)   // 768 words per row

// ---------------- scratch (static device globals; no allocation) ----------------
__device__ float g_seq[ROWS*DIN];
__device__ float g_ab [ROWS*2*DM];
__device__ float g_ac [ROWS*DM];
__device__ float g_Bm [ROWS*DS];
__device__ float g_Cm [ROWS*DS];
__device__ float g_dt [ROWS*DD];
__device__ float g_delta[ROWS*DM];
__device__ float g_wpack[NL*128*DM];

// packed bf16x2 hi/lo operands, plain K-major word order
__device__ unsigned g_xn_hi[ROWS*KW_IN],  g_xn_lo[ROWS*KW_IN];
__device__ unsigned g_so_hi[ROWS*KW_DM],  g_so_lo[ROWS*KW_DM];
__device__ unsigned g_wi_hi[NL*2*DM*KW_IN], g_wi_lo[NL*2*DM*KW_IN];
__device__ unsigned g_wo_hi[NL*DIN*KW_DM],  g_wo_lo[NL*DIN*KW_DM];
// packed fp16x2 operands for the single-pass head GEMM
__device__ unsigned g_wh_fp[VOCAB*KW_IN];
__device__ unsigned g_xn_fp[ROWS*KW_IN];

__device__ __forceinline__ float siluf(float x){ return x / (1.f + __expf(-x)); }
__device__ __forceinline__ float softplusf(float x){ return fmaxf(x,0.f) + log1pf(expf(-fabsf(x))); }

__device__ __forceinline__ unsigned pack_split(float x0, float x1, unsigned &lopair){
    __nv_bfloat16 h0 = __float2bfloat16(x0);
    __nv_bfloat16 h1 = __float2bfloat16(x1);
    float f0 = __bfloat162float(h0), f1 = __bfloat162float(h1);
    __nv_bfloat16 l0 = __float2bfloat16(x0 - f0);
    __nv_bfloat16 l1 = __float2bfloat16(x1 - f1);
    lopair = ((unsigned)__bfloat16_as_ushort(l1) << 16) | __bfloat16_as_ushort(l0);
    return ((unsigned)__bfloat16_as_ushort(h1) << 16) | __bfloat16_as_ushort(h0);
}

__device__ __forceinline__ unsigned pack_fp16(float x0, float x1){
    __half h0 = __float2half_rn(x0);
    __half h1 = __float2half_rn(x1);
    return ((unsigned)__half_as_ushort(h1) << 16) | __half_as_ushort(h0);
}

__device__ __forceinline__ void mma_bf16(float* d, const unsigned* a, const unsigned* b){
    asm volatile(
      "mma.sync.aligned.m16n8k16.row.col.f32.bf16.bf16.f32 "
      "{%0,%1,%2,%3}, {%4,%5,%6,%7}, {%8,%9}, {%0,%1,%2,%3};\n"
      : "+f"(d[0]),"+f"(d[1]),"+f"(d[2]),"+f"(d[3])
      : "r"(a[0]),"r"(a[1]),"r"(a[2]),"r"(a[3]), "r"(b[0]),"r"(b[1]));
}
__device__ __forceinline__ void mma_fp16(float* d, const unsigned* a, const unsigned* b){
    asm volatile(
      "mma.sync.aligned.m16n8k16.row.col.f32.f16.f16.f32 "
      "{%0,%1,%2,%3}, {%4,%5,%6,%7}, {%8,%9}, {%0,%1,%2,%3};\n"
      : "+f"(d[0]),"+f"(d[1]),"+f"(d[2]),"+f"(d[3])
      : "r"(a[0]),"r"(a[1]),"r"(a[2]),"r"(a[3]), "r"(b[0]),"r"(b[1]));
}

__device__ __forceinline__ void cp16(void* s, const void* g){
    unsigned a = (unsigned)__cvta_generic_to_shared(s);
    asm volatile("cp.async.cg.shared.global [%0], [%1], 16;" :: "r"(a), "l"(g));
}

// ---------------- weight split: fp32 [Nrows,K] -> packed bf16x2 hi/lo ----------------
__global__ void split_kernel(const float* __restrict__ src, unsigned* __restrict__ hi,
                             unsigned* __restrict__ lo, int totalWords, int K){
    int idx = blockIdx.x*256 + threadIdx.x;
    if (idx >= totalWords) return;
    int Kw = K >> 1;
    int n = idx / Kw, w = idx - n*Kw;
    int k = 2*w;
    float x0 = src[(size_t)n*K + k], x1 = src[(size_t)n*K + k + 1];
    unsigned l; unsigned h = pack_split(x0, x1, l);
    hi[idx] = h; lo[idx] = l;
}

// ---------------- fp16 pack: fp32 [Nrows,K] -> packed fp16x2 ----------------
__global__ void fp16_pack_kernel(const float* __restrict__ src, unsigned* __restrict__ dst,
                                 int totalWords, int K){
    int idx = blockIdx.x*256 + threadIdx.x;
    if (idx >= totalWords) return;
    int Kw = K >> 1;
    int n = idx / Kw, w = idx - n*Kw;
    int k = 2*w;
    dst[idx] = pack_fp16(src[(size_t)n*K + k], src[(size_t)n*K + k + 1]);
}

// ---------------- embedding gather ----------------
__global__ void embed_kernel(const int* __restrict__ tok, const float* __restrict__ emb){
    int row = blockIdx.x;
    int t = tok[row];
    for (int c = threadIdx.x; c < DIN; c += blockDim.x)
        g_seq[row*DIN + c] = emb[t*DIN + c];
}

// ---------------- rmsnorm -> split bf16 hi/lo (+ optional packed fp16) -----
__global__ void rmsnorm_kernel(const float* __restrict__ in, const float* __restrict__ w,
                               unsigned* __restrict__ hi, unsigned* __restrict__ lo,
                               unsigned* __restrict__ fp){
    int row = blockIdx.x;
    float ss = 0.f;
    #pragma unroll
    for (int i = 0; i < 3; i++){
        float x = in[row*DIN + threadIdx.x + i*256];
        ss += x*x;
    }
    #pragma unroll
    for (int off = 16; off > 0; off >>= 1) ss += __shfl_xor_sync(0xffffffffu, ss, off);
    __shared__ float red[8];
    if ((threadIdx.x & 31) == 0) red[threadIdx.x >> 5] = ss;
    __syncthreads();
    float ms = 0.f;
    #pragma unroll
    for (int i = 0; i < 8; i++) ms += red[i];
    float r = rsqrtf(ms * (1.f/768.f) + 1e-6f);
    for (int p = threadIdx.x; p < KW_IN; p += 256){
        int c = 2*p;
        float y0 = in[row*DIN + c]     * r * w[c];
        float y1 = in[row*DIN + c + 1] * r * w[c+1];
        if (hi){
            unsigned l; unsigned h = pack_split(y0, y1, l);
            hi[row*KW_IN + p] = h; lo[row*KW_IN + p] = l;
        }
        if (fp) fp[row*KW_IN + p] = pack_fp16(y0, y1);
    }
}

// ========== bf16x3 split GEMM, pre-split operands, cp.async double buffer (R4) ======
__global__ void __launch_bounds__(256,2) gemm_bf16s_kernel(
    const unsigned* __restrict__ Ahi, const unsigned* __restrict__ Alo,
    const unsigned* __restrict__ Bhi, const unsigned* __restrict__ Blo,
    float* __restrict__ C, int M, int N, int K,
    const float* __restrict__ bias, const float* __restrict__ resid, int act)
{
    __shared__ unsigned sm[2][4][128*8];   // [stage][Ahi,Alo,Bhi,Blo][row*8+w]
    int tid = threadIdx.x;
    int lane = tid & 31, warp = tid >> 5;
    int qr = lane >> 2, q = lane & 3;
    int m0 = (warp >> 1) * 32, n0 = (warp & 1) * 64;
    int brow = blockIdx.x * 128, bcol = blockIdx.y * 128;
    int Kw = K >> 1;
    int lrow = tid >> 1, lh = (tid & 1) << 2;
    int sidx = lrow*8 + lh;

    const unsigned* gA_hi = Ahi + (size_t)(brow + lrow)*Kw + lh;
    const unsigned* gA_lo = Alo + (size_t)(brow + lrow)*Kw + lh;
    const unsigned* gB_hi = Bhi + (size_t)(bcol + lrow)*Kw + lh;
    const unsigned* gB_lo = Blo + (size_t)(bcol + lrow)*Kw + lh;

    float acc[2][8][4];
    #pragma unroll
    for (int im = 0; im < 2; im++)
        #pragma unroll
        for (int jn = 0; jn < 8; jn++)
            #pragma unroll
            for (int e = 0; e < 4; e++) acc[im][jn][e] = 0.f;

    int kt = K >> 4;

    cp16(&sm[0][0][sidx], gA_hi);
    cp16(&sm[0][1][sidx], gA_lo);
    cp16(&sm[0][2][sidx], gB_hi);
    cp16(&sm[0][3][sidx], gB_lo);
    asm volatile("cp.async.commit_group;");

    for (int k = 0; k < kt; k++){
        int st = k & 1;
        if (k + 1 < kt){
            int s2 = (k+1) & 1;
            size_t off = (size_t)(k+1) * 8;
            cp16(&sm[s2][0][sidx], gA_hi + off);
            cp16(&sm[s2][1][sidx], gA_lo + off);
            cp16(&sm[s2][2][sidx], gB_hi + off);
            cp16(&sm[s2][3][sidx], gB_lo + off);
            asm volatile("cp.async.commit_group;");
            asm volatile("cp.async.wait_group 1;");
        } else {
            asm volatile("cp.async.wait_group 0;");
        }
        __syncthreads();

        unsigned ah[2][4], al[2][4];
        #pragma unroll
        for (int im = 0; im < 2; im++){
            int r0 = (m0 + im*16 + qr    )*8 + 2*q;
            int r1 = (m0 + im*16 + qr + 8)*8 + 2*q;
            uint2 h0 = *(const uint2*)&sm[st][0][r0];
            uint2 h1 = *(const uint2*)&sm[st][0][r1];
            ah[im][0] = h0.x; ah[im][1] = h1.x; ah[im][2] = h0.y; ah[im][3] = h1.y;
            uint2 l0 = *(const uint2*)&sm[st][1][r0];
            uint2 l1 = *(const uint2*)&sm[st][1][r1];
            al[im][0] = l0.x; al[im][1] = l1.x; al[im][2] = l0.y; al[im][3] = l1.y;
        }
        #pragma unroll
        for (int jn = 0; jn < 8; jn++){
            int rb = (n0 + jn*8 + qr)*8 + 2*q;
            uint2 bh2 = *(const uint2*)&sm[st][2][rb];
            uint2 bl2 = *(const uint2*)&sm[st][3][rb];
            unsigned bh[2] = {bh2.x, bh2.y};
            unsigned bl[2] = {bl2.x, bl2.y};
            #pragma unroll
            for (int im = 0; im < 2; im++) mma_bf16(acc[im][jn], ah[im], bh);
            #pragma unroll
            for (int im = 0; im < 2; im++) mma_bf16(acc[im][jn], ah[im], bl);
            #pragma unroll
            for (int im = 0; im < 2; im++) mma_bf16(acc[im][jn], al[im], bh);
        }
        __syncthreads();
    }

    #pragma unroll
    for (int im = 0; im < 2; im++){
        #pragma unroll
        for (int h = 0; h < 2; h++){
            int m = brow + m0 + im*16 + qr + h*8;
            #pragma unroll
            for (int jn = 0; jn < 8; jn++){
                int n = bcol + n0 + jn*8 + 2*q;
                float v0 = acc[im][jn][h*2 + 0];
                float v1 = acc[im][jn][h*2 + 1];
                if (bias){ v0 += bias[n]; v1 += bias[n+1]; }
                if (act){ v0 = softplusf(v0); v1 = softplusf(v1); }
                if (resid){ v0 += resid[(size_t)m*N + n]; v1 += resid[(size_t)m*N + n + 1]; }
                *(float2*)&C[(size_t)m*N + n] = make_float2(v0, v1);
            }
        }
    }
}

// ========== single-pass fp16 GEMM (head): C = A @ B^T, fp32 accumulate ==========
// 10-bit mantissa inputs (same precision as tf32) at full bf16 HMMA rate.
__global__ void __launch_bounds__(256,2) gemm_fp16_kernel(
    const unsigned* __restrict__ A, const unsigned* __restrict__ B,
    float* __restrict__ C, int M, int N, int K)
{
    __shared__ unsigned sm[2][2][128*8];   // [stage][A,B][row*8+w]
    int tid = threadIdx.x;
    int lane = tid & 31, warp = tid >> 5;
    int qr = lane >> 2, q = lane & 3;
    int m0 = (warp >> 1) * 32, n0 = (warp & 1) * 64;
    int brow = blockIdx.x * 128, bcol = blockIdx.y * 128;
    int Kw = K >> 1;
    int lrow = tid >> 1, lh = (tid & 1) << 2;
    int sidx = lrow*8 + lh;

    const unsigned* gA = A + (size_t)(brow + lrow)*Kw + lh;
    const unsigned* gB = B + (size_t)(bcol + lrow)*Kw + lh;

    float acc[2][8][4];
    #pragma unroll
    for (int im = 0; im < 2; im++)
        #pragma unroll
        for (int jn = 0; jn < 8; jn++)
            #pragma unroll
            for (int e = 0; e < 4; e++) acc[im][jn][e] = 0.f;

    int kt = K >> 4;

    cp16(&sm[0][0][sidx], gA);
    cp16(&sm[0][1][sidx], gB);
    asm volatile("cp.async.commit_group;");

    for (int k = 0; k < kt; k++){
        int st = k & 1;
        if (k + 1 < kt){
            int s2 = (k+1) & 1;
            size_t off = (size_t)(k+1) * 8;
            cp16(&sm[s2][0][sidx], gA + off);
            cp16(&sm[s2][1][sidx], gB + off);
            asm volatile("cp.async.commit_group;");
            asm volatile("cp.async.wait_group 1;");
        } else {
            asm volatile("cp.async.wait_group 0;");
        }
        __syncthreads();

        unsigned a[2][4];
        #pragma unroll
        for (int im = 0; im < 2; im++){
            int r0 = (m0 + im*16 + qr    )*8 + 2*q;
            int r1 = (m0 + im*16 + qr + 8)*8 + 2*q;
            uint2 h0 = *(const uint2*)&sm[st][0][r0];
            uint2 h1 = *(const uint2*)&sm[st][0][r1];
            a[im][0] = h0.x; a[im][1] = h1.x; a[im][2] = h0.y; a[im][3] = h1.y;
        }
        #pragma unroll
        for (int jn = 0; jn < 8; jn++){
            int rb = (n0 + jn*8 + qr)*8 + 2*q;
            uint2 bb = *(const uint2*)&sm[st][1][rb];
            unsigned b[2] = {bb.x, bb.y};
            #pragma unroll
            for (int im = 0; im < 2; im++) mma_fp16(acc[im][jn], a[im], b);
        }
        __syncthreads();
    }

    #pragma unroll
    for (int im = 0; im < 2; im++){
        #pragma unroll
        for (int h = 0; h < 2; h++){
            int m = brow + m0 + im*16 + qr + h*8;
            #pragma unroll
            for (int jn = 0; jn < 8; jn++){
                int n = bcol + n0 + jn*8 + 2*q;
                *(float2*)&C[(size_t)m*N + n] =
                    make_float2(acc[im][jn][h*2 + 0], acc[im][jn][h*2 + 1]);
            }
        }
    }
}

// ---------------- FFMA SGEMM (small-K delta projection; full fp32) ----------------
__global__ void __launch_bounds__(256) gemm_nt_kernel(
    const float* __restrict__ A, const float* __restrict__ Bw, float* __restrict__ C,
    int M, int N, int K,
    const float* __restrict__ bias, const float* __restrict__ resid, int act)
{
    __shared__ float As[8][128];
    __shared__ float Bs[8][128];
    int tid = threadIdx.x;
    int tx = tid & 15, ty = tid >> 4;
    int brow = blockIdx.y * 128, bcol = blockIdx.x * 128;

    const float* Aptr = A  + (size_t)(brow + (tid >> 1)) * K + ((tid & 1) << 2);
    const float* Bptr = Bw + (size_t)(bcol + (tid >> 1)) * K + ((tid & 1) << 2);

    float acc[8][8];
    #pragma unroll
    for (int i = 0; i < 8; i++)
        #pragma unroll
        for (int j = 0; j < 8; j++) acc[i][j] = 0.f;

    int kt = K >> 3;
    float4 aReg = *(const float4*)Aptr;
    float4 bReg = *(const float4*)Bptr;

    for (int k = 0; k < kt; k++){
        int r = tid >> 1, c = (tid & 1) << 2;
        As[c+0][r]=aReg.x; As[c+1][r]=aReg.y; As[c+2][r]=aReg.z; As[c+3][r]=aReg.w;
        Bs[c+0][r]=bReg.x; Bs[c+1][r]=bReg.y; Bs[c+2][r]=bReg.z; Bs[c+3][r]=bReg.w;
        __syncthreads();
        if (k + 1 < kt){
            aReg = *(const float4*)(Aptr + (k+1)*8);
            bReg = *(const float4*)(Bptr + (k+1)*8);
        }
        #pragma unroll
        for (int kk = 0; kk < 8; kk++){
            float af[8], bf[8];
            #pragma unroll
            for (int i = 0; i < 8; i++) af[i] = As[kk][(i<<4)+ty];
            #pragma unroll
            for (int j = 0; j < 8; j++) bf[j] = Bs[kk][(j<<4)+tx];
            #pragma unroll
            for (int i = 0; i < 8; i++)
                #pragma unroll
                for (int j = 0; j < 8; j++)
                    acc[i][j] += af[i]*bf[j];
        }
        __syncthreads();
    }

    #pragma unroll
    for (int i = 0; i < 8; i++){
        int m = brow + (i<<4) + ty;
        #pragma unroll
        for (int j = 0; j < 8; j++){
            int n = bcol + (j<<4) + tx;
            float v = acc[i][j];
            if (bias)  v += bias[n];
            if (act)   v = softplusf(v);
            if (resid) v += resid[(size_t)m*N + n];
            C[(size_t)m*N + n] = v;
        }
    }
}

// ---------------- causal depthwise conv (K=4) + SiLU ----------------
__global__ void conv_silu_kernel(const float* __restrict__ cw, const float* __restrict__ cb){
    int d = blockIdx.x * blockDim.x + threadIdx.x;
    int row = blockIdx.y;
    int t = row & (LL-1);
    float4 w = *(const float4*)(cw + d*4);
    float acc = cb[d];
    const float* p = g_ab + (size_t)row*(2*DM) + d;
    if (t >= 3) acc += p[-3*2*DM]*w.x;
    if (t >= 2) acc += p[-2*2*DM]*w.y;
    if (t >= 1) acc += p[-1*2*DM]*w.z;
    acc += p[0]*w.w;
    g_ac[(size_t)row*DM + d] = siluf(acc);
}

// ---------------- pack sB|sC|sD0 into one [NL][128][DM] weight ----------------
__global__ void pack_kernel(const float* __restrict__ sB, const float* __restrict__ sC,
                            const float* __restrict__ sD0){
    int idx = blockIdx.x*256 + threadIdx.x;
    if (idx >= NL*128*DM) return;
    int k = idx % DM;
    int n = (idx / DM) & 127;
    int l = idx / (128*DM);
    float v;
    if (n < 16)      v = sB [((size_t)l*DS + n     )*DM + k];
    else if (n < 32) v = sC [((size_t)l*DS + (n-16))*DM + k];
    else             v = sD0[((size_t)l*DD + (n-32))*DM + k];
    g_wpack[idx] = v;
}

// ---------------- fused small projections: [16 rows] x [128 outs], K=1536 ----------------
#define SP_KC 64
__global__ void __launch_bounds__(256) small_proj_kernel(const float* __restrict__ wp){
    __shared__ float Ws[128][SP_KC+1];
    __shared__ float Xs[16][SP_KC+4];
    int m0  = blockIdx.x * 16;
    int tid = threadIdx.x;
    int n2  = tid & 63;
    int mh  = tid >> 6;
    float acc[2][4] = {{0.f,0.f,0.f,0.f},{0.f,0.f,0.f,0.f}};

    for (int k0 = 0; k0 < DM; k0 += SP_KC){
        #pragma unroll
        for (int j = 0; j < 8; j++){
            int idx = tid + j*256;
            int r = idx >> 4, c4 = (idx & 15) << 2;
            float4 v = *(const float4*)(wp + (size_t)r*DM + k0 + c4);
            Ws[r][c4+0]=v.x; Ws[r][c4+1]=v.y; Ws[r][c4+2]=v.z; Ws[r][c4+3]=v.w;
        }
        {
            int r = tid >> 4, c4 = (tid & 15) << 2;
            float4 v = *(const float4*)(g_ac + (size_t)(m0+r)*DM + k0 + c4);
            Xs[r][c4+0]=v.x; Xs[r][c4+1]=v.y; Xs[r][c4+2]=v.z; Xs[r][c4+3]=v.w;
        }
        __syncthreads();
        #pragma unroll 8
        for (int kk = 0; kk < SP_KC; kk++){
            float w0 = Ws[2*n2][kk], w1 = Ws[2*n2+1][kk];
            #pragma unroll
            for (int i = 0; i < 4; i++){
                float x = Xs[mh*4+i][kk];
                acc[0][i] += w0*x;
                acc[1][i] += w1*x;
            }
        }
        __syncthreads();
    }
    #pragma unroll
    for (int q = 0; q < 2; q++){
        int n = 2*n2 + q;
        #pragma unroll
        for (int i = 0; i < 4; i++){
            int m = m0 + mh*4 + i;
            float v = acc[q][i];
            if (n < 16)      g_Bm[m*DS + n]      = v;
            else if (n < 32) g_Cm[m*DS + (n-16)] = v;
            else             g_dt[m*DD + (n-32)] = v;
        }
    }
}

// ---------------- selective scan (writes split bf16 sout, plain order) ----------------
__global__ void scan_kernel(const float* __restrict__ A_log, const float* __restrict__ Dp){
    int lane = threadIdx.x & 31, warp = threadIdx.x >> 5;
    int s = lane & 15;
    int d = blockIdx.x*8 + warp*2 + (lane >> 4);
    int b = blockIdx.y;
    float Acoef = -expf(A_log[d*DS + s]);
    float Dv = Dp[d];
    int base  = (b*LL)*DM + d;
    int baseS = (b*LL)*DS + s;
    int baseG = (b*LL)*(2*DM) + DM + d;
    float dlt = g_delta[base], av = g_ac[base];
    float Bv = g_Bm[baseS], Cv = g_Cm[baseS];
    float gv = g_ab[baseG];
    float h = 0.f;
    int p = blockIdx.x*4 + warp;            // d-pair index within DM/2
    int wbase = (b*LL)*KW_DM + p;
    for (int t = 0; t < LL; t++){
        float dc = dlt, a_c = av, bc = Bv, cc = Cv, gc = gv;
        if (t + 1 < LL){
            base += DM; baseS += DS; baseG += 2*DM;
            dlt = g_delta[base]; av = g_ac[base];
            Bv = g_Bm[baseS];   Cv = g_Cm[baseS];
            gv = g_ab[baseG];
        }
        h = __expf(dc*Acoef)*h + dc*bc*a_c;
        float c = h*cc;
        c += __shfl_xor_sync(0xffffffffu, c, 8);
        c += __shfl_xor_sync(0xffffffffu, c, 4);
        c += __shfl_xor_sync(0xffffffffu, c, 2);
        c += __shfl_xor_sync(0xffffffffu, c, 1);
        float o = (c + Dv*a_c) * siluf(gc);
        float o2 = __shfl_xor_sync(0xffffffffu, o, 16);
        if (lane == 0){
            unsigned l; unsigned hh = pack_split(o, o2, l);
            g_so_hi[wbase + t*KW_DM] = hh;
            g_so_lo[wbase + t*KW_DM] = l;
        }
    }
}

// ---------------- launch ----------------
extern "C" void kernel_launch(void* const* d_in, const int* in_sizes, int n_in,
                              void* d_out, int out_size)
{
    const int*   tok      = (const int*)  d_in[0];
    const float* emb      = (const float*)d_in[1];
    const float* in_proj  = (const float*)d_in[2];
    const float* out_proj = (const float*)d_in[3];
    const float* sB       = (const float*)d_in[4];
    const float* sC       = (const float*)d_in[5];
    const float* sD0      = (const float*)d_in[6];
    const float* sD1w     = (const float*)d_in[7];
    const float* sD1b     = (const float*)d_in[8];
    const float* cw       = (const float*)d_in[9];
    const float* cb       = (const float*)d_in[10];
    const float* A_log    = (const float*)d_in[11];
    const float* Dp       = (const float*)d_in[12];
    const float* norm_w   = (const float*)d_in[13];
    const float* norm_f   = (const float*)d_in[14];
    const float* head_w   = (const float*)d_in[15];
    float* out = (float*)d_out;

    float *seq,*ab,*ac,*dt,*delta,*wpack;
    unsigned *xnh,*xnl,*soh,*sol,*wih,*wil,*woh,*wol,*whf,*xnf;
    cudaGetSymbolAddress((void**)&seq,   g_seq);
    cudaGetSymbolAddress((void**)&ab,    g_ab);
    cudaGetSymbolAddress((void**)&ac,    g_ac);
    cudaGetSymbolAddress((void**)&dt,    g_dt);
    cudaGetSymbolAddress((void**)&delta, g_delta);
    cudaGetSymbolAddress((void**)&wpack, g_wpack);
    cudaGetSymbolAddress((void**)&xnh, g_xn_hi); cudaGetSymbolAddress((void**)&xnl, g_xn_lo);
    cudaGetSymbolAddress((void**)&soh, g_so_hi); cudaGetSymbolAddress((void**)&sol, g_so_lo);
    cudaGetSymbolAddress((void**)&wih, g_wi_hi); cudaGetSymbolAddress((void**)&wil, g_wi_lo);
    cudaGetSymbolAddress((void**)&woh, g_wo_hi); cudaGetSymbolAddress((void**)&wol, g_wo_lo);
    cudaGetSymbolAddress((void**)&whf, g_wh_fp); cudaGetSymbolAddress((void**)&xnf, g_xn_fp);

    embed_kernel<<<ROWS, 256>>>(tok, emb);
    pack_kernel<<<(NL*128*DM + 255)/256, 256>>>(sB, sC, sD0);
    split_kernel<<<(NL*2*DM*KW_IN + 255)/256, 256>>>(in_proj,  wih, wil, NL*2*DM*KW_IN, DIN);
    split_kernel<<<(NL*DIN*KW_DM  + 255)/256, 256>>>(out_proj, woh, wol, NL*DIN*KW_DM,  DM);
    fp16_pack_kernel<<<(VOCAB*KW_IN + 255)/256, 256>>>(head_w, whf, VOCAB*KW_IN, DIN);

    for (int l = 0; l < NL; l++){
        rmsnorm_kernel<<<ROWS, 256>>>(seq, norm_w + l*DIN, xnh, xnl, nullptr);
        // ab = xn @ in_proj^T   (2048 x 3072, K=768)  [bf16x3]
        gemm_bf16s_kernel<<<dim3(ROWS/128, 2*DM/128), 256>>>(
            xnh, xnl, wih + (size_t)l*2*DM*KW_IN, wil + (size_t)l*2*DM*KW_IN,
            ab, ROWS, 2*DM, DIN, nullptr, nullptr, 0);
        conv_silu_kernel<<<dim3(DM/256, ROWS), 256>>>(cw + l*DM*4, cb + l*DM);
        small_proj_kernel<<<ROWS/16, 256>>>(wpack + (size_t)l*128*DM);
        // delta = softplus(dt @ sD1w^T + sD1b)   (2048 x 1536, K=96)  [fp32 FFMA]
        gemm_nt_kernel<<<dim3(DM/128, ROWS/128), 256>>>(
            dt, sD1w + (size_t)l*DM*DD, delta, ROWS, DM, DD, sD1b + l*DM, nullptr, 1);
        scan_kernel<<<dim3(DM/8, BB), 128>>>(A_log + (size_t)l*DM*DS, Dp + l*DM);
        // seq = sout @ out_proj^T + seq   (2048 x 768, K=1536)  [bf16x3]
        gemm_bf16s_kernel<<<dim3(ROWS/128, DIN/128), 256>>>(
            soh, sol, woh + (size_t)l*DIN*KW_DM, wol + (size_t)l*DIN*KW_DM,
            seq, ROWS, DIN, DM, nullptr, seq, 0);
    }

    rmsnorm_kernel<<<ROWS, 256>>>(seq, norm_f, nullptr, nullptr, xnf);
    // logits = xn @ head_w^T   (2048 x 32000, K=768)  [fp16 single pass]
    gemm_fp16_kernel<<<dim3(ROWS/128, VOCAB/128), 256>>>(
        xnf, whf, out, ROWS, VOCAB, DIN);
}